// round 17
// baseline (speedup 1.0000x reference)
#include <cuda_runtime.h>
#include <cuda_fp16.h>
#include <cstdint>
#include <math.h>

#define T_STEPS 256
#define INPUT   12288
#define HID     1024
#define GATES   4096

#define LO_SCALE 2048.0f
#define INV_LO   (1.0f / 2048.0f)

// ---------------- device scratch (no allocations allowed) ----------------
__device__ unsigned long long g_hp[2][HID];        // {epoch|h} ping-pong
__device__ __half g_Ahi[T_STEPS * INPUT];          // frames fp16 hi

// ---------------- helpers ----------------
__device__ __forceinline__ void ffma2(unsigned long long& d,
                                      unsigned long long a,
                                      unsigned long long b) {
    asm("fma.rn.f32x2 %0, %1, %2, %0;" : "+l"(d) : "l"(a), "l"(b));
}
__device__ __forceinline__ void unpack2(unsigned long long v, float& lo, float& hi) {
    asm("mov.b64 {%0, %1}, %2;" : "=f"(lo), "=f"(hi) : "l"(v));
}
__device__ __forceinline__ void cvt_pair_h(float f0, float f1,
                                           unsigned int& h01, unsigned int& l01) {
    __half2 h = __floats2half2_rn(f0, f1);
    float e0 = (f0 - __half2float(__low2half(h)))  * LO_SCALE;
    float e1 = (f1 - __half2float(__high2half(h))) * LO_SCALE;
    __half2 l = __floats2half2_rn(e0, e1);
    h01 = *reinterpret_cast<unsigned int*>(&h);
    l01 = *reinterpret_cast<unsigned int*>(&l);
}
__device__ __forceinline__ unsigned int cvt_hi2(float f0, float f1) {
    __half2 h = __floats2half2_rn(f0, f1);
    return *reinterpret_cast<unsigned int*>(&h);
}
__device__ __forceinline__ void lm4(uint32_t& d0, uint32_t& d1, uint32_t& d2,
                                    uint32_t& d3, uint32_t addr) {
    asm volatile("ldmatrix.sync.aligned.m8n8.x4.shared.b16 {%0,%1,%2,%3}, [%4];"
                 : "=r"(d0), "=r"(d1), "=r"(d2), "=r"(d3) : "r"(addr));
}
__device__ __forceinline__ void mma_f16_f32acc(float c[4], const uint32_t a[4],
                                               const uint32_t b[2]) {
    asm volatile(
        "mma.sync.aligned.m16n8k16.row.col.f32.f16.f16.f32 "
        "{%0,%1,%2,%3}, {%4,%5,%6,%7}, {%8,%9}, {%0,%1,%2,%3};"
        : "+f"(c[0]), "+f"(c[1]), "+f"(c[2]), "+f"(c[3])
        : "r"(a[0]), "r"(a[1]), "r"(a[2]), "r"(a[3]), "r"(b[0]), "r"(b[1]));
}
__device__ __forceinline__ void mma_f16_f16acc(uint32_t c[2], const uint32_t a[4],
                                               const uint32_t b[2]) {
    asm volatile(
        "mma.sync.aligned.m16n8k16.row.col.f16.f16.f16.f16 "
        "{%0,%1}, {%2,%3,%4,%5}, {%6,%7}, {%0,%1};"
        : "+r"(c[0]), "+r"(c[1])
        : "r"(a[0]), "r"(a[1]), "r"(a[2]), "r"(a[3]), "r"(b[0]), "r"(b[1]));
}
__device__ __forceinline__ uint32_t smem_u32(const void* p) {
    uint32_t a;
    asm("{ .reg .u64 t; cvta.to.shared.u64 t, %1; cvt.u32.u64 %0, t; }" : "=r"(a) : "l"(p));
    return a;
}
__device__ __forceinline__ unsigned long long ld_rlx(const unsigned long long* p) {
    unsigned long long v;
    asm volatile("ld.relaxed.gpu.global.u64 %0, [%1];" : "=l"(v) : "l"(p) : "memory");
    return v;
}
__device__ __forceinline__ void st_rlx(unsigned long long* p, unsigned long long v) {
    asm volatile("st.relaxed.gpu.global.u64 [%0], %1;" :: "l"(p), "l"(v) : "memory");
}
__device__ __forceinline__ float fast_sigmoid(float x) {
    return __fdividef(1.f, 1.f + __expf(-x));
}
__device__ __forceinline__ float fast_tanh(float x) {
    float e = __expf(-2.f * x);
    return __fdividef(1.f - e, 1.f + e);
}
__device__ __forceinline__ int ld_vol_s32(uint32_t addr) {
    int v;
    asm volatile("ld.volatile.shared.s32 %0, [%1];" : "=r"(v) : "r"(addr) : "memory");
    return v;
}
__device__ __forceinline__ void st_vol_s32(uint32_t addr, int v) {
    asm volatile("st.volatile.shared.s32 [%0], %1;" :: "r"(addr), "r"(v) : "memory");
}
#define BARX(id, cnt) asm volatile("bar.sync %0, %1;" :: "r"(id), "r"(cnt) : "memory")

// ---------------- splitA (+ init of h buffers) ----------------
__global__ __launch_bounds__(256)
void splitA_kernel(const float* __restrict__ A) {
    const int NA = T_STEPS * INPUT / 4;
    int gid = blockIdx.x * blockDim.x + threadIdx.x;
    if (gid < HID) { g_hp[0][gid] = 0ULL; g_hp[1][gid] = 0ULL; }
    int stride = gridDim.x * blockDim.x;
    for (int i = gid; i < NA; i += stride) {
        float4 v = ((const float4*)A)[i];
        uint2 hi;
        hi.x = cvt_hi2(v.x, v.y);
        hi.y = cvt_hi2(v.z, v.w);
        ((uint2*)g_Ahi)[i] = hi;
    }
}

// ---------------- fused warp-specialized kernel ----------------
// 128 CTAs x 384 threads. Warps 0-7: scan (unit j = 8b+w). Warps 8-11: GEMM
// producing this CTA's 32 gate columns into smem xp[256][33], 8 m-blocks of 32
// rows, readiness via volatile smem counter.
#define GK 64
#define NCHB (INPUT / GK)       // 192 chunks per m-block
#define NMB 8                   // m-blocks
#define PITCH 144               // staged row bytes (128 data + 16 pad)
#define MAT_B (32 * PITCH)      // 4608
#define STG_B (3 * MAT_B)       // 13824  (A, Bh, Bl)
#define XP_P  33
#define SM_XP    0
#define SM_STAGE 33792          // 256*33*4
#define SM_HS    (SM_STAGE + 2 * STG_B)     // 61440
#define SM_BIAS  (SM_HS + 2 * HID * 4)      // 69632
#define SM_XRDY  (SM_BIAS + 128)            // 69760
#define FUSED_SMEM (SM_XRDY + 128)          // 69888
#define OFF_A  0
#define OFF_BH MAT_B
#define OFF_BL (2 * MAT_B)

__global__ __launch_bounds__(384, 1)
void fused_kernel(const float* __restrict__ A16_unused,
                  const float* __restrict__ W,
                  const float* __restrict__ Whh,
                  const float* __restrict__ b_ih,
                  const float* __restrict__ b_hh) {
    extern __shared__ char smem[];
    float* xp     = (float*)(smem + SM_XP);
    float* bias_s = (float*)(smem + SM_BIAS);
    const uint32_t sbase   = smem_u32(smem);
    const uint32_t xrdy_a  = sbase + SM_XRDY;

    const int tid  = threadIdx.x;
    const int warp = tid >> 5;
    const int lane = tid & 31;
    const int b    = blockIdx.x;

    if (warp < 8) {
        // ================= SCAN WARPS (threads 0-255) =================
        const int j = b * 8 + warp;
        float* hsbuf = (float*)(smem + SM_HS);

        unsigned long long wreg[4][8][2];
#pragma unroll
        for (int g = 0; g < 4; g++) {
            const float* wrow = Whh + (size_t)(g * HID + j) * HID;
#pragma unroll
            for (int i = 0; i < 8; i++) {
                ulonglong2 v = *(const ulonglong2*)&wrow[lane * 4 + i * 128];
                wreg[g][i][0] = v.x;
                wreg[g][i][1] = v.y;
            }
        }

        float cstate = 0.f;

        for (int t = 0; t < T_STEPS; t++) {
            // ---- wait for xp block (t>>5) ----
            const int need = (t >> 5) + 1;
            while (ld_vol_s32(xrdy_a) < need) { }
            // xg reads (after poll; asm memory clobber orders them)
            float xg0 = xp[t * XP_P + 0 + warp];
            float xg1 = xp[t * XP_P + 8 + warp];
            float xg2 = xp[t * XP_P + 16 + warp];
            float xg3 = xp[t * XP_P + 24 + warp];

            // ---- acquire h_t (busy-spin payload poll, R15 champion) ----
            const unsigned long long* p0 = g_hp[t & 1] + tid;
            const unsigned int want = (unsigned int)t;
            unsigned long long v0, v1, v2, v3;
            bool ok;
            do {
                v0 = ld_rlx(p0);
                v1 = ld_rlx(p0 + 256);
                v2 = ld_rlx(p0 + 512);
                v3 = ld_rlx(p0 + 768);
                ok = ((unsigned int)(v0 >> 32) == want) &
                     ((unsigned int)(v1 >> 32) == want) &
                     ((unsigned int)(v2 >> 32) == want) &
                     ((unsigned int)(v3 >> 32) == want);
            } while (!ok);
            float* cur = hsbuf + (t & 1) * HID;
            cur[tid]       = __uint_as_float((unsigned int)v0);
            cur[tid + 256] = __uint_as_float((unsigned int)v1);
            cur[tid + 512] = __uint_as_float((unsigned int)v2);
            cur[tid + 768] = __uint_as_float((unsigned int)v3);
            BARX(2, 256);

            unsigned long long a2[4] = {0ULL, 0ULL, 0ULL, 0ULL};
#pragma unroll
            for (int i = 0; i < 8; i++) {
                ulonglong2 h2 = *(const ulonglong2*)&cur[lane * 4 + i * 128];
#pragma unroll
                for (int g = 0; g < 4; g++) {
                    ffma2(a2[g], h2.x, wreg[g][i][0]);
                    ffma2(a2[g], h2.y, wreg[g][i][1]);
                }
            }

            float red[4];
#pragma unroll
            for (int g = 0; g < 4; g++) {
                float lo, hi;
                unpack2(a2[g], lo, hi);
                red[g] = lo + hi;
            }
#pragma unroll
            for (int o = 16; o; o >>= 1) {
#pragma unroll
                for (int g = 0; g < 4; g++)
                    red[g] += __shfl_xor_sync(0xffffffffu, red[g], o);
            }

            float gi = fast_sigmoid(xg0 + red[0]);
            float gf = fast_sigmoid(xg1 + red[1]);
            float gg = fast_tanh(xg2 + red[2]);
            float go = fast_sigmoid(xg3 + red[3]);
            cstate = gf * cstate + gi * gg;
            float hnew = go * fast_tanh(cstate);

            if (lane == 0) {
                unsigned long long pk =
                    ((unsigned long long)(unsigned int)(t + 1) << 32) |
                    (unsigned long long)__float_as_uint(hnew);
                st_rlx(&g_hp[(t + 1) & 1][j], pk);
            }
        }
    } else {
        // ================= GEMM WARPS (threads 256-383) =================
        const int gt = tid - 256;          // 0..127
        const int w2 = warp - 8;           // 0..3
        const int wm = (w2 & 1) * 16;
        const int wn = (w2 >> 1) * 16;
        const int g  = lane >> 2;
        const int tg = lane & 3;
        char* stg = smem + SM_STAGE;

        // init: xready=0, biases
        if (gt == 0) st_vol_s32(xrdy_a, 0);
        if (gt < 32) {
            int gidx = (gt >> 3) * 1024 + b * 8 + (gt & 7);
            bias_s[gt] = b_ih[gidx] + b_hh[gidx];
        }

        // ldmatrix per-lane offsets (pitch 144)
        const uint32_t aOff = (uint32_t)((wm + ((lane >> 3) & 1) * 8 + (lane & 7)) * PITCH
                                         + (lane >> 4) * 16);
        const uint32_t bOff = (uint32_t)((wn + (lane >> 4) * 8 + (lane & 7)) * PITCH
                                         + ((lane >> 3) & 1) * 16);

        // global-load mappings
        int arow[2], acl[2];
#pragma unroll
        for (int p = 0; p < 2; p++) { int idx = gt + p * 128; arow[p] = idx >> 3; acl[p] = idx & 7; }
        int brow[4], bcl[4], gRow[4];
#pragma unroll
        for (int p = 0; p < 4; p++) {
            int idx = gt + p * 128;
            brow[p] = idx >> 4; bcl[p] = idx & 15;
            gRow[p] = (brow[p] >> 3) * 1024 + b * 8 + (brow[p] & 7);
        }

        float    acc [2][4];
        uint32_t accC[2][2];
#pragma unroll
        for (int nt = 0; nt < 2; nt++) {
#pragma unroll
            for (int q = 0; q < 4; q++) acc[nt][q] = 0.f;
            accC[nt][0] = 0u; accC[nt][1] = 0u;
        }

        uint4 pA[2];
        float4 pW[4];

        // prologue: LDG chunk 0 (mb=0, k0=0), STS -> stage 0
#pragma unroll
        for (int p = 0; p < 2; p++)
            pA[p] = *(const uint4*)(g_Ahi + (size_t)arow[p] * INPUT + acl[p] * 8);
#pragma unroll
        for (int p = 0; p < 4; p++)
            pW[p] = *(const float4*)(W + (size_t)gRow[p] * INPUT + bcl[p] * 4);
        {
            char* s0 = stg;
#pragma unroll
            for (int p = 0; p < 2; p++)
                *(uint4*)(s0 + OFF_A + arow[p] * PITCH + acl[p] * 16) = pA[p];
#pragma unroll
            for (int p = 0; p < 4; p++) {
                uint2 h, l;
                cvt_pair_h(pW[p].x, pW[p].y, h.x, l.x);
                cvt_pair_h(pW[p].z, pW[p].w, h.y, l.y);
                uint32_t e = brow[p] * PITCH + bcl[p] * 8;
                *(uint2*)(s0 + OFF_BH + e) = h;
                *(uint2*)(s0 + OFF_BL + e) = l;
            }
        }
        BARX(1, 128);

        const int NTOT = NMB * NCHB;   // 1536 chunks
        for (int c = 0; c < NTOT; c++) {
            const int buf = c & 1;
            // prefetch chunk c+1
            if (c + 1 < NTOT) {
                int cn = c + 1;
                int mbN = cn / NCHB;
                int k0N = (cn % NCHB) * GK;
#pragma unroll
                for (int p = 0; p < 2; p++)
                    pA[p] = *(const uint4*)(g_Ahi + (size_t)(mbN * 32 + arow[p]) * INPUT
                                            + k0N + acl[p] * 8);
#pragma unroll
                for (int p = 0; p < 4; p++)
                    pW[p] = *(const float4*)(W + (size_t)gRow[p] * INPUT + k0N + bcl[p] * 4);
            }

            // compute 4 k16 steps on stage buf
            const uint32_t st = sbase + SM_STAGE + buf * STG_B;
#pragma unroll
            for (int kk = 0; kk < 4; kk++) {
                const uint32_t kb = kk * 32;
                uint32_t ah[4], bh[4], bl[4];
                lm4(ah[0], ah[1], ah[2], ah[3], st + OFF_A + aOff + kb);
                lm4(bh[0], bh[1], bh[2], bh[3], st + OFF_BH + bOff + kb);
                lm4(bl[0], bl[1], bl[2], bl[3], st + OFF_BL + bOff + kb);
#pragma unroll
                for (int nt = 0; nt < 2; nt++) {
                    mma_f16_f32acc(acc[nt], ah, &bh[nt * 2]);
                    mma_f16_f16acc(accC[nt], ah, &bl[nt * 2]);
                }
            }

            const bool blockEnd = ((c + 1) % NCHB) == 0;
            if (blockEnd) {
                // epilogue: acc -> xp (+bias), reset
                int mb = c / NCHB;
                int t0 = mb * 32 + wm + g;
#pragma unroll
                for (int nt = 0; nt < 2; nt++) {
                    int n = wn + nt * 8 + tg * 2;
                    float2 c01 = __half22float2(*reinterpret_cast<__half2*>(&accC[nt][0]));
                    float2 c23 = __half22float2(*reinterpret_cast<__half2*>(&accC[nt][1]));
                    float bi0 = bias_s[n], bi1 = bias_s[n + 1];
                    xp[t0 * XP_P + n]           = acc[nt][0] + c01.x * INV_LO + bi0;
                    xp[t0 * XP_P + n + 1]       = acc[nt][1] + c01.y * INV_LO + bi1;
                    xp[(t0 + 8) * XP_P + n]     = acc[nt][2] + c23.x * INV_LO + bi0;
                    xp[(t0 + 8) * XP_P + n + 1] = acc[nt][3] + c23.y * INV_LO + bi1;
                    acc[nt][0] = acc[nt][1] = acc[nt][2] = acc[nt][3] = 0.f;
                    accC[nt][0] = 0u; accC[nt][1] = 0u;
                }
            }

            // STS chunk c+1 into other stage
            if (c + 1 < NTOT) {
                char* sn = stg + ((c + 1) & 1) * STG_B;
#pragma unroll
                for (int p = 0; p < 2; p++)
                    *(uint4*)(sn + OFF_A + arow[p] * PITCH + acl[p] * 16) = pA[p];
#pragma unroll
                for (int p = 0; p < 4; p++) {
                    uint2 h, l;
                    cvt_pair_h(pW[p].x, pW[p].y, h.x, l.x);
                    cvt_pair_h(pW[p].z, pW[p].w, h.y, l.y);
                    uint32_t e = brow[p] * PITCH + bcl[p] * 8;
                    *(uint2*)(sn + OFF_BH + e) = h;
                    *(uint2*)(sn + OFF_BL + e) = l;
                }
            }
            BARX(1, 128);   // xp + stage stores drained CTA-wide
            if (blockEnd && gt == 0)
                st_vol_s32(xrdy_a, c / NCHB + 1);
        }
    }
}

// ---------------- final: out = h_T @ fc_w^T + fc_b ----------------
__global__ __launch_bounds__(256, 2)
void final_kernel(const float* __restrict__ fcw,
                  const float* __restrict__ fcb,
                  float* __restrict__ out) {
    __shared__ float hs[HID];
    const int tid = threadIdx.x, warp = tid >> 5, lane = tid & 31;
#pragma unroll
    for (int q = 0; q < 4; q++)
        hs[tid + q * 256] = __uint_as_float((unsigned int)g_hp[0][tid + q * 256]);
    __syncthreads();

    int row = blockIdx.x * 16 + warp * 2;
    const float* wr0 = fcw + (size_t)row * HID;
    const float* wr1 = wr0 + HID;
    float acc0 = 0.f, acc1 = 0.f;
#pragma unroll
    for (int i = 0; i < 8; i++) {
        float4 h4 = *(const float4*)&hs[lane * 4 + i * 128];
        float4 a4 = *(const float4*)&wr0[lane * 4 + i * 128];
        float4 b4 = *(const float4*)&wr1[lane * 4 + i * 128];
        acc0 += a4.x * h4.x + a4.y * h4.y + a4.z * h4.z + a4.w * h4.w;
        acc1 += b4.x * h4.x + b4.y * h4.y + b4.z * h4.z + b4.w * h4.w;
    }
#pragma unroll
    for (int o = 16; o; o >>= 1) {
        acc0 += __shfl_xor_sync(0xffffffffu, acc0, o);
        acc1 += __shfl_xor_sync(0xffffffffu, acc1, o);
    }
    if (lane == 0) {
        out[row]     = acc0 + fcb[row];
        out[row + 1] = acc1 + fcb[row + 1];
    }
}

// ---------------- launch ----------------
extern "C" void kernel_launch(void* const* d_in, const int* in_sizes, int n_in,
                              void* d_out, int out_size) {
    const float* frames = (const float*)d_in[0];
    const float* W_ih   = (const float*)d_in[1];
    const float* W_hh   = (const float*)d_in[2];
    const float* b_ih   = (const float*)d_in[3];
    const float* b_hh   = (const float*)d_in[4];
    const float* fc_w   = (const float*)d_in[5];
    const float* fc_b   = (const float*)d_in[6];
    float* out = (float*)d_out;

    cudaFuncSetAttribute(fused_kernel,
                         cudaFuncAttributeMaxDynamicSharedMemorySize, FUSED_SMEM);

    splitA_kernel<<<1024, 256>>>(frames);   // also zeroes g_hp epochs

    fused_kernel<<<128, 384, FUSED_SMEM>>>(nullptr, W_ih, W_hh, b_ih, b_hh);

    final_kernel<<<12288 / 16, 256>>>(fc_w, fc_b, out);
}